// round 15
// baseline (speedup 1.0000x reference)
#include <cuda_runtime.h>
#include <cuda_fp16.h>
#include <cstdint>
#include <math_constants.h>

// ============================================================================
// TransformerBlock, all-1-term fp16 GEMMs on mma.sync (HMMA), sm_103-safe ISA.
//   Projections: x_h @ w_h^T + b   (K=1024)
//   Scores:      q_h @ k_h^T / 32  (K=1024)
//   P@V:         p_h @ v_h^T       (K=4096)
// R15: register double-buffered LDSM fragments in the GEMM mainloop (prefetch
// kk+1 while MMAs of kk execute); weight converts merged into one launch.
// GEMM core: 128x128 CTA tile, BK=64, 2-stage cp.async ring, 4 warps
// (64x64 each), 2 CTAs/SM, 2-pass SMEM epilogue.
// ============================================================================

#define S_LEN 4096
#define D_DIM 1024

// ---------------- device scratch (no allocs allowed) ------------------------
__device__ __align__(128) __half g_xh [(size_t)S_LEN * D_DIM];
__device__ __align__(128) __half g_wqh[(size_t)D_DIM * D_DIM];
__device__ __align__(128) __half g_wkh[(size_t)D_DIM * D_DIM];
__device__ __align__(128) __half g_wvh[(size_t)D_DIM * D_DIM];
__device__ __align__(128) __half g_qh [(size_t)S_LEN * D_DIM];
__device__ __align__(128) __half g_kh [(size_t)S_LEN * D_DIM];
__device__ __align__(128) __half g_vt [(size_t)D_DIM * S_LEN]; // v_h^T
__device__ __align__(128) float  g_p  [(size_t)S_LEN * S_LEN];
__device__ __align__(128) __half g_ph [(size_t)S_LEN * S_LEN]; // p_h

// ---------------- helpers ----------------------------------------------------
__device__ __forceinline__ uint32_t smem_u32(const void* p) {
    uint32_t a;
    asm("{ .reg .u64 t; cvta.to.shared.u64 t, %1; cvt.u32.u64 %0, t; }"
        : "=r"(a) : "l"(p));
    return a;
}
#define SMEM_SWIZZLE_128B(o) ((o) ^ (((o) >> 3) & 0x70))

__device__ __forceinline__ void cp16(uint32_t dst, const void* src) {
    asm volatile("cp.async.cg.shared.global [%0], [%1], 16;" :: "r"(dst), "l"(src));
}
__device__ __forceinline__ void ldsm_x4(uint32_t (&r)[4], uint32_t addr) {
    asm volatile("ldmatrix.sync.aligned.m8n8.x4.shared.b16 {%0,%1,%2,%3}, [%4];"
        : "=r"(r[0]), "=r"(r[1]), "=r"(r[2]), "=r"(r[3]) : "r"(addr));
}
__device__ __forceinline__ void mma16816(float (&c)[4], const uint32_t (&a)[4],
                                         uint32_t b0, uint32_t b1) {
    asm volatile(
        "mma.sync.aligned.m16n8k16.row.col.f32.f16.f16.f32 "
        "{%0,%1,%2,%3}, {%4,%5,%6,%7}, {%8,%9}, {%0,%1,%2,%3};"
        : "+f"(c[0]), "+f"(c[1]), "+f"(c[2]), "+f"(c[3])
        : "r"(a[0]), "r"(a[1]), "r"(a[2]), "r"(a[3]), "r"(b0), "r"(b1));
}

// ============================================================================
// GEMM: 128x128 CTA tile, BK=64, 2-stage ring, 4 warps (64x64 each), 2 CTA/SM.
// MODE 0: fp32 out, scaled by alpha
// MODE 1: fp16 out + bias (bias indexed by output column)
// MODE 2: fp16 out + bias, transposed store (bias indexed by output row = n)
// ============================================================================
constexpr int STAGES = 2;
constexpr int NTHR = 128;
constexpr int SMEM_BYTES = 1024 + STAGES * 32768;   // 66560 -> 2 CTAs/SM

template <int MODE>
__global__ void __launch_bounds__(NTHR, 2)
gemm_f16(const __half* __restrict__ A, int lda,
         const __half* __restrict__ B, int ldb,
         float* __restrict__ Cf, __half* __restrict__ Ch, int ldc,
         const float* __restrict__ bias, float alpha, int ntiles)
{
    extern __shared__ char smem[];
    const uint32_t sbase = smem_u32(smem);
    const int tid  = threadIdx.x;
    const int wid  = tid >> 5;
    const int lane = tid & 31;
    const int bm = blockIdx.y * 128, bn = blockIdx.x * 128;

    // 2 warps along M, 2 along N; 64x64 per warp
    const int wm = (wid & 1) * 64;
    const int wn = (wid >> 1) * 64;

    const char* Arow = (const char*)A + (size_t)bm * lda * 2;
    const char* Brow = (const char*)B + (size_t)bn * ldb * 2;
    const size_t ldab = (size_t)lda * 2, ldbb = (size_t)ldb * 2;

    auto load_stage = [&](int t, int slot) {
        const uint32_t sA = sbase + 1024 + slot * 32768;
        const uint32_t sB = sA + 16384;
        const size_t koff = (size_t)t * 128;  // t*64 elems * 2B
#pragma unroll
        for (int j = 0; j < 8; j++) {
            const int idx = tid + j * NTHR;         // 0..1023
            const int r = idx >> 3, c = idx & 7;    // 128 rows x 8 chunks (16B)
            const uint32_t so = SMEM_SWIZZLE_128B((uint32_t)(r * 128 + c * 16));
            cp16(sA + so, Arow + (size_t)r * ldab + koff + c * 16);
            cp16(sB + so, Brow + (size_t)r * ldbb + koff + c * 16);
        }
    };

    float c[4][8][4];
#pragma unroll
    for (int i = 0; i < 4; i++)
#pragma unroll
        for (int j = 0; j < 8; j++)
#pragma unroll
            for (int r = 0; r < 4; r++) c[i][j][r] = 0.0f;

    const uint32_t xswz = (uint32_t)(lane & 7) << 4;
    const uint32_t selA = (uint32_t)(lane >> 4) << 4;
    const uint32_t selB = (uint32_t)((lane >> 3) & 1) << 4;
    const int aRowOff = lane & 15;
    const int bRowOff = ((lane >> 4) << 3) + (lane & 7);

    // double-buffered fragments
    uint32_t afrag[2][4][4];
    uint32_t bfrag[2][8][2];

    // prologue: stage 0 in flight
    load_stage(0, 0);
    asm volatile("cp.async.commit_group;" ::: "memory");

    for (int i = 0; i < ntiles; i++) {
        const int slot = i & 1;
        asm volatile("cp.async.wait_group 0;" ::: "memory");
        __syncthreads();
        if (i + 1 < ntiles) load_stage(i + 1, slot ^ 1);
        asm volatile("cp.async.commit_group;" ::: "memory");

        // ---- compute on slot (cp.async of next stage overlaps)
        {
            const uint32_t sA = sbase + 1024 + slot * 32768;
            const uint32_t sB = sA + 16384;
            uint32_t aBase[4], bBase[4];
#pragma unroll
            for (int tm = 0; tm < 4; tm++)
                aBase[tm] = sA + (uint32_t)(wm + tm * 16 + aRowOff) * 128;
#pragma unroll
            for (int tb = 0; tb < 4; tb++)
                bBase[tb] = sB + (uint32_t)(wn + tb * 16 + bRowOff) * 128;

            auto ld_frags = [&](int kk, int buf) {
                const uint32_t cbA = ((uint32_t)(kk * 32) + selA) ^ xswz;
                const uint32_t cbB = ((uint32_t)(kk * 32) + selB) ^ xswz;
#pragma unroll
                for (int tm = 0; tm < 4; tm++)
                    ldsm_x4(afrag[buf][tm], aBase[tm] + cbA);
#pragma unroll
                for (int tb = 0; tb < 4; tb++) {
                    uint32_t r4[4];
                    ldsm_x4(r4, bBase[tb] + cbB);
                    bfrag[buf][2 * tb][0] = r4[0]; bfrag[buf][2 * tb][1] = r4[1];
                    bfrag[buf][2 * tb + 1][0] = r4[2]; bfrag[buf][2 * tb + 1][1] = r4[3];
                }
            };

            ld_frags(0, 0);
#pragma unroll
            for (int kk = 0; kk < 4; kk++) {
                const int cur = kk & 1;
                if (kk < 3) ld_frags(kk + 1, cur ^ 1);   // prefetch next k-step
#pragma unroll
                for (int tm = 0; tm < 4; tm++)
#pragma unroll
                    for (int tn = 0; tn < 8; tn++)
                        mma16816(c[tm][tn], afrag[cur][tm],
                                 bfrag[cur][tn][0], bfrag[cur][tn][1]);
            }
        }
    }
    asm volatile("cp.async.wait_group 0;" ::: "memory");
    __syncthreads();

    // ---------------- 2-pass epilogue: regs -> SMEM (64 rows) -> gmem ---------
    float* epi = reinterpret_cast<float*>(smem + 1024);
    constexpr int EP = 132;
    const int gr = lane >> 2;
    const int gc = (lane & 3) * 2;

#pragma unroll
    for (int h = 0; h < 2; h++) {
        const bool mine = ((MODE == 2 ? wn : wm) >> 6) == h;
        if (mine) {
#pragma unroll
            for (int tm = 0; tm < 4; tm++) {
#pragma unroll
                for (int tn = 0; tn < 8; tn++) {
                    const int m = wm + tm * 16 + gr;
                    const int n = wn + tn * 8 + gc;
                    const float* cc = c[tm][tn];
                    if constexpr (MODE == 2) {
                        const int nl = n - h * 64;
                        epi[nl * EP + m]           = cc[0];
                        epi[(nl + 1) * EP + m]     = cc[1];
                        epi[nl * EP + m + 8]       = cc[2];
                        epi[(nl + 1) * EP + m + 8] = cc[3];
                    } else {
                        const int ml = m - h * 64;
                        *reinterpret_cast<float2*>(&epi[ml * EP + n]) =
                            make_float2(cc[0], cc[1]);
                        *reinterpret_cast<float2*>(&epi[(ml + 8) * EP + n]) =
                            make_float2(cc[2], cc[3]);
                    }
                }
            }
        }
        __syncthreads();

#pragma unroll 4
        for (int it = 0; it < 16; it++) {
            const int g = tid + it * NTHR;      // 0..2047
            const int rl = g >> 5;              // 0..63
            const int row = h * 64 + rl;        // MODE2: n index; else m index
            const int c4 = (g & 31) << 2;
            float4 v = *reinterpret_cast<const float4*>(&epi[rl * EP + c4]);
            if constexpr (MODE == 0) {
                v.x *= alpha; v.y *= alpha; v.z *= alpha; v.w *= alpha;
                *reinterpret_cast<float4*>(&Cf[(size_t)(bm + row) * ldc + bn + c4]) = v;
            } else if constexpr (MODE == 2) {
                const float b0 = bias[bn + row];
                const __half2 hA = __halves2half2(__float2half_rn(v.x + b0),
                                                  __float2half_rn(v.y + b0));
                const __half2 hB = __halves2half2(__float2half_rn(v.z + b0),
                                                  __float2half_rn(v.w + b0));
                const size_t base = (size_t)(bn + row) * ldc + bm + c4;
                *reinterpret_cast<__half2*>(&Ch[base])     = hA;
                *reinterpret_cast<__half2*>(&Ch[base + 2]) = hB;
            } else {
                const __half2 hA = __halves2half2(
                    __float2half_rn(v.x + bias[bn + c4 + 0]),
                    __float2half_rn(v.y + bias[bn + c4 + 1]));
                const __half2 hB = __halves2half2(
                    __float2half_rn(v.z + bias[bn + c4 + 2]),
                    __float2half_rn(v.w + bias[bn + c4 + 3]));
                const size_t base = (size_t)(bm + row) * ldc + bn + c4;
                *reinterpret_cast<__half2*>(&Ch[base])     = hA;
                *reinterpret_cast<__half2*>(&Ch[base + 2]) = hB;
            }
        }
        __syncthreads();
    }
}

// ============================================================================
// cvt: fp32 -> fp16, single tensor
// ============================================================================
__global__ void __launch_bounds__(256)
cvt_h_kernel(const float* __restrict__ in, __half* __restrict__ out)
{
    const size_t idx = ((size_t)blockIdx.x * 256 + threadIdx.x) * 4;
    const float4 v = *reinterpret_cast<const float4*>(&in[idx]);
    *reinterpret_cast<__half2*>(&out[idx]) =
        __halves2half2(__float2half_rn(v.x), __float2half_rn(v.y));
    *reinterpret_cast<__half2*>(&out[idx + 2]) =
        __halves2half2(__float2half_rn(v.z), __float2half_rn(v.w));
}

// cvt3: three weight tensors in one launch (blockIdx.y selects)
__global__ void __launch_bounds__(256)
cvt3_h_kernel(const float* __restrict__ a, const float* __restrict__ b,
              const float* __restrict__ cc,
              __half* __restrict__ oa, __half* __restrict__ ob,
              __half* __restrict__ oc)
{
    const float* in  = (blockIdx.y == 0) ? a  : (blockIdx.y == 1) ? b  : cc;
    __half*      out = (blockIdx.y == 0) ? oa : (blockIdx.y == 1) ? ob : oc;
    const size_t idx = ((size_t)blockIdx.x * 256 + threadIdx.x) * 4;
    const float4 v = *reinterpret_cast<const float4*>(&in[idx]);
    *reinterpret_cast<__half2*>(&out[idx]) =
        __halves2half2(__float2half_rn(v.x), __float2half_rn(v.y));
    *reinterpret_cast<__half2*>(&out[idx + 2]) =
        __halves2half2(__float2half_rn(v.z), __float2half_rn(v.w));
}

// ============================================================================
// softmax rows of P[4096,4096] fp32 -> p_h fp16 [4096,4096]
// ============================================================================
__global__ void __launch_bounds__(256)
softmax_h_kernel(const float* __restrict__ P, __half* __restrict__ Ph)
{
    __shared__ float red[16];
    const float* row = P + (size_t)blockIdx.x * S_LEN;
    const int tid = threadIdx.x, lane = tid & 31, warp = tid >> 5;

    float vals[16];
    float m = -CUDART_INF_F;
#pragma unroll
    for (int i = 0; i < 4; i++) {
        float4 v = *reinterpret_cast<const float4*>(&row[i * 1024 + tid * 4]);
        vals[i * 4 + 0] = v.x; vals[i * 4 + 1] = v.y;
        vals[i * 4 + 2] = v.z; vals[i * 4 + 3] = v.w;
        m = fmaxf(m, fmaxf(fmaxf(v.x, v.y), fmaxf(v.z, v.w)));
    }
#pragma unroll
    for (int o = 16; o > 0; o >>= 1) m = fmaxf(m, __shfl_xor_sync(0xffffffffu, m, o));
    if (lane == 0) red[warp] = m;
    __syncthreads();
    float m_all = red[0];
#pragma unroll
    for (int i = 1; i < 8; i++) m_all = fmaxf(m_all, red[i]);

    float s = 0.0f;
#pragma unroll
    for (int i = 0; i < 16; i++) {
        vals[i] = __expf(vals[i] - m_all);
        s += vals[i];
    }
#pragma unroll
    for (int o = 16; o > 0; o >>= 1) s += __shfl_xor_sync(0xffffffffu, s, o);
    if (lane == 0) red[8 + warp] = s;
    __syncthreads();
    float s_all = red[8];
#pragma unroll
    for (int i = 1; i < 8; i++) s_all += red[8 + i];
    const float inv = 1.0f / s_all;

    __half* orow = Ph + (size_t)blockIdx.x * S_LEN;
#pragma unroll
    for (int i = 0; i < 4; i++) {
        const int cix = i * 1024 + tid * 4;
        const __half2 a = __halves2half2(__float2half_rn(vals[i * 4 + 0] * inv),
                                         __float2half_rn(vals[i * 4 + 1] * inv));
        const __half2 b = __halves2half2(__float2half_rn(vals[i * 4 + 2] * inv),
                                         __float2half_rn(vals[i * 4 + 3] * inv));
        *reinterpret_cast<__half2*>(&orow[cix])     = a;
        *reinterpret_cast<__half2*>(&orow[cix + 2]) = b;
    }
}

// ============================================================================
// launch (graph-capturable). Inputs: [0]=x [1]=wq [2]=bq [3]=wk [4]=bk [5]=wv [6]=bv
// ============================================================================
extern "C" void kernel_launch(void* const* d_in, const int* in_sizes, int n_in,
                              void* d_out, int out_size)
{
    const float* x  = (const float*)d_in[0];
    const float* wq = (const float*)d_in[1];
    const float* bq = (const float*)d_in[2];
    const float* wk = (const float*)d_in[3];
    const float* bk = (const float*)d_in[4];
    const float* wv = (const float*)d_in[5];
    const float* bv = (const float*)d_in[6];
    float* out = (float*)d_out;

    __half *xh, *wqh, *wkh, *wvh, *qh, *kh, *vt, *ph;
    float* P;
    cudaGetSymbolAddress((void**)&xh,  g_xh);
    cudaGetSymbolAddress((void**)&wqh, g_wqh);
    cudaGetSymbolAddress((void**)&wkh, g_wkh);
    cudaGetSymbolAddress((void**)&wvh, g_wvh);
    cudaGetSymbolAddress((void**)&qh,  g_qh);
    cudaGetSymbolAddress((void**)&kh,  g_kh);
    cudaGetSymbolAddress((void**)&vt,  g_vt);
    cudaGetSymbolAddress((void**)&P,   g_p);
    cudaGetSymbolAddress((void**)&ph,  g_ph);

    cudaFuncSetAttribute(gemm_f16<0>, cudaFuncAttributeMaxDynamicSharedMemorySize, SMEM_BYTES);
    cudaFuncSetAttribute(gemm_f16<1>, cudaFuncAttributeMaxDynamicSharedMemorySize, SMEM_BYTES);
    cudaFuncSetAttribute(gemm_f16<2>, cudaFuncAttributeMaxDynamicSharedMemorySize, SMEM_BYTES);

    // ---- fp32 -> fp16 converts (x + merged weights)
    cvt_h_kernel<<<(S_LEN * D_DIM / 4) / 256, 256>>>(x, xh);
    {
        dim3 g((D_DIM * D_DIM / 4) / 256, 3);
        cvt3_h_kernel<<<g, 256>>>(wq, wk, wv, wqh, wkh, wvh);
    }

    const dim3 gProj(D_DIM / 128, S_LEN / 128);   // (8, 32)
    const dim3 gScore(S_LEN / 128, S_LEN / 128);  // (32, 32)

    // ---- projections: x_h @ w_h^T + b   (K=1024)
    gemm_f16<1><<<gProj, NTHR, SMEM_BYTES>>>(xh, D_DIM, wqh, D_DIM, nullptr, qh,
                                             D_DIM, bq, 1.0f, D_DIM / 64);
    gemm_f16<1><<<gProj, NTHR, SMEM_BYTES>>>(xh, D_DIM, wkh, D_DIM, nullptr, kh,
                                             D_DIM, bk, 1.0f, D_DIM / 64);
    gemm_f16<2><<<gProj, NTHR, SMEM_BYTES>>>(xh, D_DIM, wvh, D_DIM, nullptr, vt,
                                             S_LEN, bv, 1.0f, D_DIM / 64);  // v_h^T

    // ---- scores: P = (q_h k_h^T) / 32   (K=1024)
    gemm_f16<0><<<gScore, NTHR, SMEM_BYTES>>>(qh, D_DIM, kh, D_DIM, P, nullptr,
                                              S_LEN, nullptr, 0.03125f,
                                              D_DIM / 64);

    // ---- softmax -> p_h
    softmax_h_kernel<<<S_LEN, 256>>>(P, ph);

    // ---- out = p_h @ v_h^T   (K=4096)
    gemm_f16<0><<<gProj, NTHR, SMEM_BYTES>>>(ph, S_LEN, vt, S_LEN, out, nullptr,
                                             D_DIM, nullptr, 1.0f,
                                             S_LEN / 64);
}

// round 16
// speedup vs baseline: 1.0230x; 1.0230x over previous
#include <cuda_runtime.h>
#include <cuda_fp16.h>
#include <cstdint>
#include <math_constants.h>

// ============================================================================
// TransformerBlock, all-1-term fp16 GEMMs on mma.sync (HMMA), sm_103-safe ISA.
//   Projections (fused single launch, grid.z selects q/k/v): x_h @ w_h^T + b
//   Scores:      q_h @ k_h^T / 32  (K=1024)
//   P@V:         p_h @ v_h^T       (K=4096)
// R16: revert R15 frag double-buffering (neutral, +regs); fuse 3 projection
// launches into one (768 CTAs = 2.6 waves vs 3x0.86 with 20 idle SMs); fuse
// all fp32->fp16 converts into one launch. 5 launches total (was 8).
// GEMM core: 128x128 CTA tile, BK=64, 2-stage cp.async ring, 4 warps
// (64x64 each), 2 CTAs/SM, 2-pass SMEM epilogue.
// ============================================================================

#define S_LEN 4096
#define D_DIM 1024

// ---------------- device scratch (no allocs allowed) ------------------------
__device__ __align__(128) __half g_xh [(size_t)S_LEN * D_DIM];
__device__ __align__(128) __half g_wqh[(size_t)D_DIM * D_DIM];
__device__ __align__(128) __half g_wkh[(size_t)D_DIM * D_DIM];
__device__ __align__(128) __half g_wvh[(size_t)D_DIM * D_DIM];
__device__ __align__(128) __half g_qh [(size_t)S_LEN * D_DIM];
__device__ __align__(128) __half g_kh [(size_t)S_LEN * D_DIM];
__device__ __align__(128) __half g_vt [(size_t)D_DIM * S_LEN]; // v_h^T
__device__ __align__(128) float  g_p  [(size_t)S_LEN * S_LEN];
__device__ __align__(128) __half g_ph [(size_t)S_LEN * S_LEN]; // p_h

// ---------------- helpers ----------------------------------------------------
__device__ __forceinline__ uint32_t smem_u32(const void* p) {
    uint32_t a;
    asm("{ .reg .u64 t; cvta.to.shared.u64 t, %1; cvt.u32.u64 %0, t; }"
        : "=r"(a) : "l"(p));
    return a;
}
#define SMEM_SWIZZLE_128B(o) ((o) ^ (((o) >> 3) & 0x70))

__device__ __forceinline__ void cp16(uint32_t dst, const void* src) {
    asm volatile("cp.async.cg.shared.global [%0], [%1], 16;" :: "r"(dst), "l"(src));
}
__device__ __forceinline__ void ldsm_x4(uint32_t (&r)[4], uint32_t addr) {
    asm volatile("ldmatrix.sync.aligned.m8n8.x4.shared.b16 {%0,%1,%2,%3}, [%4];"
        : "=r"(r[0]), "=r"(r[1]), "=r"(r[2]), "=r"(r[3]) : "r"(addr));
}
__device__ __forceinline__ void mma16816(float (&c)[4], const uint32_t (&a)[4],
                                         uint32_t b0, uint32_t b1) {
    asm volatile(
        "mma.sync.aligned.m16n8k16.row.col.f32.f16.f16.f32 "
        "{%0,%1,%2,%3}, {%4,%5,%6,%7}, {%8,%9}, {%0,%1,%2,%3};"
        : "+f"(c[0]), "+f"(c[1]), "+f"(c[2]), "+f"(c[3])
        : "r"(a[0]), "r"(a[1]), "r"(a[2]), "r"(a[3]), "r"(b0), "r"(b1));
}

constexpr int STAGES = 2;
constexpr int NTHR = 128;
constexpr int SMEM_BYTES = 1024 + STAGES * 32768;   // 66560 -> 2 CTAs/SM

// ============================================================================
// Shared GEMM core: mainloop accumulates c[4][8][4] for a 128x128 CTA tile.
// ============================================================================
struct GemmCtx {
    uint32_t sbase;
    int tid, wid, lane, wm, wn;
    uint32_t xswz, selA, selB;
    int aRowOff, bRowOff;
};

__device__ __forceinline__ void gemm_mainloop(
    const GemmCtx& g, const __half* A, int lda, const __half* B, int ldb,
    int bm, int bn, int ntiles, float (&c)[4][8][4])
{
    const char* Arow = (const char*)A + (size_t)bm * lda * 2;
    const char* Brow = (const char*)B + (size_t)bn * ldb * 2;
    const size_t ldab = (size_t)lda * 2, ldbb = (size_t)ldb * 2;

    auto load_stage = [&](int t, int slot) {
        const uint32_t sA = g.sbase + 1024 + slot * 32768;
        const uint32_t sB = sA + 16384;
        const size_t koff = (size_t)t * 128;
#pragma unroll
        for (int j = 0; j < 8; j++) {
            const int idx = g.tid + j * NTHR;
            const int r = idx >> 3, ch = idx & 7;
            const uint32_t so = SMEM_SWIZZLE_128B((uint32_t)(r * 128 + ch * 16));
            cp16(sA + so, Arow + (size_t)r * ldab + koff + ch * 16);
            cp16(sB + so, Brow + (size_t)r * ldbb + koff + ch * 16);
        }
    };

    load_stage(0, 0);
    asm volatile("cp.async.commit_group;" ::: "memory");

    for (int i = 0; i < ntiles; i++) {
        const int slot = i & 1;
        asm volatile("cp.async.wait_group 0;" ::: "memory");
        __syncthreads();
        if (i + 1 < ntiles) load_stage(i + 1, slot ^ 1);
        asm volatile("cp.async.commit_group;" ::: "memory");

        const uint32_t sA = g.sbase + 1024 + slot * 32768;
        const uint32_t sB = sA + 16384;
        uint32_t aBase[4], bBase[4];
#pragma unroll
        for (int tm = 0; tm < 4; tm++)
            aBase[tm] = sA + (uint32_t)(g.wm + tm * 16 + g.aRowOff) * 128;
#pragma unroll
        for (int tb = 0; tb < 4; tb++)
            bBase[tb] = sB + (uint32_t)(g.wn + tb * 16 + g.bRowOff) * 128;

#pragma unroll
        for (int kk = 0; kk < 4; kk++) {
            const uint32_t cbA = ((uint32_t)(kk * 32) + g.selA) ^ g.xswz;
            const uint32_t cbB = ((uint32_t)(kk * 32) + g.selB) ^ g.xswz;
            uint32_t a[4][4];
            uint32_t b[8][2];
#pragma unroll
            for (int tm = 0; tm < 4; tm++) ldsm_x4(a[tm], aBase[tm] + cbA);
#pragma unroll
            for (int tb = 0; tb < 4; tb++) {
                uint32_t r4[4];
                ldsm_x4(r4, bBase[tb] + cbB);
                b[2 * tb][0] = r4[0]; b[2 * tb][1] = r4[1];
                b[2 * tb + 1][0] = r4[2]; b[2 * tb + 1][1] = r4[3];
            }
#pragma unroll
            for (int tm = 0; tm < 4; tm++)
#pragma unroll
                for (int tn = 0; tn < 8; tn++)
                    mma16816(c[tm][tn], a[tm], b[tn][0], b[tn][1]);
        }
    }
    asm volatile("cp.async.wait_group 0;" ::: "memory");
    __syncthreads();
}

__device__ __forceinline__ GemmCtx make_ctx(char* smem) {
    GemmCtx g;
    g.sbase = smem_u32(smem);
    g.tid = threadIdx.x;
    g.wid = g.tid >> 5;
    g.lane = g.tid & 31;
    g.wm = (g.wid & 1) * 64;
    g.wn = (g.wid >> 1) * 64;
    g.xswz = (uint32_t)(g.lane & 7) << 4;
    g.selA = (uint32_t)(g.lane >> 4) << 4;
    g.selB = (uint32_t)((g.lane >> 3) & 1) << 4;
    g.aRowOff = g.lane & 15;
    g.bRowOff = ((g.lane >> 4) << 3) + (g.lane & 7);
    return g;
}

// ============================================================================
// Fused projection kernel: grid (8, 32, 3). z: 0=q (MODE1), 1=k (MODE1),
// 2=v (MODE2 transposed). All share A = xh.
// ============================================================================
__global__ void __launch_bounds__(NTHR, 2)
proj_fused(const __half* __restrict__ xh,
           const __half* __restrict__ wqh, const __half* __restrict__ wkh,
           const __half* __restrict__ wvh,
           const float* __restrict__ bq, const float* __restrict__ bk,
           const float* __restrict__ bv,
           __half* __restrict__ qh, __half* __restrict__ kh,
           __half* __restrict__ vt)
{
    extern __shared__ char smem[];
    GemmCtx g = make_ctx(smem);
    const int bm = blockIdx.y * 128, bn = blockIdx.x * 128;
    const int z = blockIdx.z;

    const __half* W    = (z == 0) ? wqh : (z == 1) ? wkh : wvh;
    const float*  bias = (z == 0) ? bq  : (z == 1) ? bk  : bv;

    float c[4][8][4];
#pragma unroll
    for (int i = 0; i < 4; i++)
#pragma unroll
        for (int j = 0; j < 8; j++)
#pragma unroll
            for (int r = 0; r < 4; r++) c[i][j][r] = 0.0f;

    gemm_mainloop(g, xh, D_DIM, W, D_DIM, bm, bn, D_DIM / 64, c);

    // 2-pass epilogue through SMEM
    float* epi = reinterpret_cast<float*>(smem + 1024);
    constexpr int EP = 132;
    const int gr = g.lane >> 2;
    const int gc = (g.lane & 3) * 2;
    const bool transposed = (z == 2);

#pragma unroll
    for (int h = 0; h < 2; h++) {
        const bool mine = ((transposed ? g.wn : g.wm) >> 6) == h;
        if (mine) {
#pragma unroll
            for (int tm = 0; tm < 4; tm++) {
#pragma unroll
                for (int tn = 0; tn < 8; tn++) {
                    const int m = g.wm + tm * 16 + gr;
                    const int n = g.wn + tn * 8 + gc;
                    const float* cc = c[tm][tn];
                    if (transposed) {
                        const int nl = n - h * 64;
                        epi[nl * EP + m]           = cc[0];
                        epi[(nl + 1) * EP + m]     = cc[1];
                        epi[nl * EP + m + 8]       = cc[2];
                        epi[(nl + 1) * EP + m + 8] = cc[3];
                    } else {
                        const int ml = m - h * 64;
                        *reinterpret_cast<float2*>(&epi[ml * EP + n]) =
                            make_float2(cc[0], cc[1]);
                        *reinterpret_cast<float2*>(&epi[(ml + 8) * EP + n]) =
                            make_float2(cc[2], cc[3]);
                    }
                }
            }
        }
        __syncthreads();

#pragma unroll 4
        for (int it = 0; it < 16; it++) {
            const int gg = g.tid + it * NTHR;
            const int rl = gg >> 5;
            const int row = h * 64 + rl;
            const int c4 = (gg & 31) << 2;
            float4 v = *reinterpret_cast<const float4*>(&epi[rl * EP + c4]);
            if (transposed) {
                const float b0 = bias[bn + row];
                const __half2 hA = __halves2half2(__float2half_rn(v.x + b0),
                                                  __float2half_rn(v.y + b0));
                const __half2 hB = __halves2half2(__float2half_rn(v.z + b0),
                                                  __float2half_rn(v.w + b0));
                const size_t base = (size_t)(bn + row) * S_LEN + bm + c4;
                *reinterpret_cast<__half2*>(&vt[base])     = hA;
                *reinterpret_cast<__half2*>(&vt[base + 2]) = hB;
            } else {
                __half* Ch = (z == 0) ? qh : kh;
                const __half2 hA = __halves2half2(
                    __float2half_rn(v.x + bias[bn + c4 + 0]),
                    __float2half_rn(v.y + bias[bn + c4 + 1]));
                const __half2 hB = __halves2half2(
                    __float2half_rn(v.z + bias[bn + c4 + 2]),
                    __float2half_rn(v.w + bias[bn + c4 + 3]));
                const size_t base = (size_t)(bm + row) * D_DIM + bn + c4;
                *reinterpret_cast<__half2*>(&Ch[base])     = hA;
                *reinterpret_cast<__half2*>(&Ch[base + 2]) = hB;
            }
        }
        __syncthreads();
    }
}

// ============================================================================
// fp32-output GEMM (scores, PV): alpha scaling
// ============================================================================
__global__ void __launch_bounds__(NTHR, 2)
gemm_f32out(const __half* __restrict__ A, int lda,
            const __half* __restrict__ B, int ldb,
            float* __restrict__ Cf, int ldc, float alpha, int ntiles)
{
    extern __shared__ char smem[];
    GemmCtx g = make_ctx(smem);
    const int bm = blockIdx.y * 128, bn = blockIdx.x * 128;

    float c[4][8][4];
#pragma unroll
    for (int i = 0; i < 4; i++)
#pragma unroll
        for (int j = 0; j < 8; j++)
#pragma unroll
            for (int r = 0; r < 4; r++) c[i][j][r] = 0.0f;

    gemm_mainloop(g, A, lda, B, ldb, bm, bn, ntiles, c);

    float* epi = reinterpret_cast<float*>(smem + 1024);
    constexpr int EP = 132;
    const int gr = g.lane >> 2;
    const int gc = (g.lane & 3) * 2;

#pragma unroll
    for (int h = 0; h < 2; h++) {
        if ((g.wm >> 6) == h) {
#pragma unroll
            for (int tm = 0; tm < 4; tm++) {
#pragma unroll
                for (int tn = 0; tn < 8; tn++) {
                    const int ml = g.wm + tm * 16 + gr - h * 64;
                    const int n = g.wn + tn * 8 + gc;
                    const float* cc = c[tm][tn];
                    *reinterpret_cast<float2*>(&epi[ml * EP + n]) =
                        make_float2(cc[0], cc[1]);
                    *reinterpret_cast<float2*>(&epi[(ml + 8) * EP + n]) =
                        make_float2(cc[2], cc[3]);
                }
            }
        }
        __syncthreads();

#pragma unroll 4
        for (int it = 0; it < 16; it++) {
            const int gg = g.tid + it * NTHR;
            const int rl = gg >> 5;
            const int row = h * 64 + rl;
            const int c4 = (gg & 31) << 2;
            float4 v = *reinterpret_cast<const float4*>(&epi[rl * EP + c4]);
            v.x *= alpha; v.y *= alpha; v.z *= alpha; v.w *= alpha;
            *reinterpret_cast<float4*>(&Cf[(size_t)(bm + row) * ldc + bn + c4]) = v;
        }
        __syncthreads();
    }
}

// ============================================================================
// cvt_all: all four fp32->fp16 converts in one flat launch.
// Blocks [0, 4096) -> x; [4096, 5120) -> wq; [5120, 6144) -> wk; rest -> wv.
// ============================================================================
__global__ void __launch_bounds__(256)
cvt_all_kernel(const float* __restrict__ x,
               const float* __restrict__ wq, const float* __restrict__ wk,
               const float* __restrict__ wv,
               __half* __restrict__ xh,
               __half* __restrict__ wqh, __half* __restrict__ wkh,
               __half* __restrict__ wvh)
{
    const int b = blockIdx.x;
    const float* in;
    __half* out;
    int lb;
    if (b < 4096)      { in = x;  out = xh;  lb = b; }
    else if (b < 5120) { in = wq; out = wqh; lb = b - 4096; }
    else if (b < 6144) { in = wk; out = wkh; lb = b - 5120; }
    else               { in = wv; out = wvh; lb = b - 6144; }
    const size_t idx = ((size_t)lb * 256 + threadIdx.x) * 4;
    const float4 v = *reinterpret_cast<const float4*>(&in[idx]);
    *reinterpret_cast<__half2*>(&out[idx]) =
        __halves2half2(__float2half_rn(v.x), __float2half_rn(v.y));
    *reinterpret_cast<__half2*>(&out[idx + 2]) =
        __halves2half2(__float2half_rn(v.z), __float2half_rn(v.w));
}

// ============================================================================
// softmax rows of P[4096,4096] fp32 -> p_h fp16 [4096,4096]
// ============================================================================
__global__ void __launch_bounds__(256)
softmax_h_kernel(const float* __restrict__ P, __half* __restrict__ Ph)
{
    __shared__ float red[16];
    const float* row = P + (size_t)blockIdx.x * S_LEN;
    const int tid = threadIdx.x, lane = tid & 31, warp = tid >> 5;

    float vals[16];
    float m = -CUDART_INF_F;
#pragma unroll
    for (int i = 0; i < 4; i++) {
        float4 v = *reinterpret_cast<const float4*>(&row[i * 1024 + tid * 4]);
        vals[i * 4 + 0] = v.x; vals[i * 4 + 1] = v.y;
        vals[i * 4 + 2] = v.z; vals[i * 4 + 3] = v.w;
        m = fmaxf(m, fmaxf(fmaxf(v.x, v.y), fmaxf(v.z, v.w)));
    }
#pragma unroll
    for (int o = 16; o > 0; o >>= 1) m = fmaxf(m, __shfl_xor_sync(0xffffffffu, m, o));
    if (lane == 0) red[warp] = m;
    __syncthreads();
    float m_all = red[0];
#pragma unroll
    for (int i = 1; i < 8; i++) m_all = fmaxf(m_all, red[i]);

    float s = 0.0f;
#pragma unroll
    for (int i = 0; i < 16; i++) {
        vals[i] = __expf(vals[i] - m_all);
        s += vals[i];
    }
#pragma unroll
    for (int o = 16; o > 0; o >>= 1) s += __shfl_xor_sync(0xffffffffu, s, o);
    if (lane == 0) red[8 + warp] = s;
    __syncthreads();
    float s_all = red[8];
#pragma unroll
    for (int i = 1; i < 8; i++) s_all += red[8 + i];
    const float inv = 1.0f / s_all;

    __half* orow = Ph + (size_t)blockIdx.x * S_LEN;
#pragma unroll
    for (int i = 0; i < 4; i++) {
        const int cix = i * 1024 + tid * 4;
        const __half2 a = __halves2half2(__float2half_rn(vals[i * 4 + 0] * inv),
                                         __float2half_rn(vals[i * 4 + 1] * inv));
        const __half2 b = __halves2half2(__float2half_rn(vals[i * 4 + 2] * inv),
                                         __float2half_rn(vals[i * 4 + 3] * inv));
        *reinterpret_cast<__half2*>(&orow[cix])     = a;
        *reinterpret_cast<__half2*>(&orow[cix + 2]) = b;
    }
}

// ============================================================================
// launch (graph-capturable). Inputs: [0]=x [1]=wq [2]=bq [3]=wk [4]=bk [5]=wv [6]=bv
// ============================================================================
extern "C" void kernel_launch(void* const* d_in, const int* in_sizes, int n_in,
                              void* d_out, int out_size)
{
    const float* x  = (const float*)d_in[0];
    const float* wq = (const float*)d_in[1];
    const float* bq = (const float*)d_in[2];
    const float* wk = (const float*)d_in[3];
    const float* bk = (const float*)d_in[4];
    const float* wv = (const float*)d_in[5];
    const float* bv = (const float*)d_in[6];
    float* out = (float*)d_out;

    __half *xh, *wqh, *wkh, *wvh, *qh, *kh, *vt, *ph;
    float* P;
    cudaGetSymbolAddress((void**)&xh,  g_xh);
    cudaGetSymbolAddress((void**)&wqh, g_wqh);
    cudaGetSymbolAddress((void**)&wkh, g_wkh);
    cudaGetSymbolAddress((void**)&wvh, g_wvh);
    cudaGetSymbolAddress((void**)&qh,  g_qh);
    cudaGetSymbolAddress((void**)&kh,  g_kh);
    cudaGetSymbolAddress((void**)&vt,  g_vt);
    cudaGetSymbolAddress((void**)&P,   g_p);
    cudaGetSymbolAddress((void**)&ph,  g_ph);

    cudaFuncSetAttribute(proj_fused,  cudaFuncAttributeMaxDynamicSharedMemorySize, SMEM_BYTES);
    cudaFuncSetAttribute(gemm_f32out, cudaFuncAttributeMaxDynamicSharedMemorySize, SMEM_BYTES);

    // ---- all converts, one launch (4096 + 3*1024 = 7168 blocks)
    cvt_all_kernel<<<7168, 256>>>(x, wq, wk, wv, xh, wqh, wkh, wvh);

    // ---- fused projections: q/k/v in one launch (grid.z selects)
    {
        dim3 g(D_DIM / 128, S_LEN / 128, 3);   // (8, 32, 3) = 768 CTAs
        proj_fused<<<g, NTHR, SMEM_BYTES>>>(xh, wqh, wkh, wvh, bq, bk, bv,
                                            qh, kh, vt);
    }

    // ---- scores: P = (q_h k_h^T) / 32   (K=1024)
    {
        dim3 g(S_LEN / 128, S_LEN / 128);      // (32, 32)
        gemm_f32out<<<g, NTHR, SMEM_BYTES>>>(qh, D_DIM, kh, D_DIM, P,
                                             S_LEN, 0.03125f, D_DIM / 64);
    }

    // ---- softmax -> p_h
    softmax_h_kernel<<<S_LEN, 256>>>(P, ph);

    // ---- out = p_h @ v_h^T   (K=4096)
    {
        dim3 g(D_DIM / 128, S_LEN / 128);      // (8, 32)
        gemm_f32out<<<g, NTHR, SMEM_BYTES>>>(ph, S_LEN, vt, S_LEN, out,
                                             D_DIM, 1.0f, S_LEN / 64);
    }
}